// round 3
// baseline (speedup 1.0000x reference)
#include <cuda_runtime.h>
#include <math.h>

#define NN 100000
#define NE 3200000
#define F_IN 512
#define F_HID 256
#define F_OUT 16
#define KSTEPS 10
#define ALPHA 0.1f

// ---- static scratch (no dynamic allocation allowed) ----
__device__ float g_h1[(size_t)NN * F_HID];   // 102.4 MB
__device__ float g_h [NN * F_OUT];
__device__ float g_zA[NN * F_OUT];
__device__ float g_zB[NN * F_OUT];
__device__ float g_dinv[NN];
__device__ int   g_counts[NN];
__device__ int   g_ptr[NN + 1];
__device__ int   g_cursor[NN];
__device__ int   g_csrc[NE];
__device__ float g_cw[NE];

// ------------------------------------------------------------------
// CSR construction  (edge_index is int32: JAX default without x64)
// ------------------------------------------------------------------
__global__ void __launch_bounds__(256) k_zero_counts() {
    int i = blockIdx.x * blockDim.x + threadIdx.x;
    if (i < NN) g_counts[i] = 0;
}

__global__ void __launch_bounds__(256) k_count(const int* __restrict__ dst) {
    int e = blockIdx.x * blockDim.x + threadIdx.x;
    if (e < NE) atomicAdd(&g_counts[dst[e]], 1);
}

__global__ void __launch_bounds__(256) k_dinv() {
    int i = blockIdx.x * blockDim.x + threadIdx.x;
    if (i < NN) g_dinv[i] = rsqrtf((float)(g_counts[i] + 1));  // +1 self loop
}

// single-block 2-level scan: 1024 threads, ~98 elements each
__global__ void __launch_bounds__(1024, 1) k_scan() {
    __shared__ int sums[1024];
    const int CH = (NN + 1023) / 1024;   // 98
    int t = threadIdx.x;
    int start = t * CH;
    int s = 0;
    for (int i = 0; i < CH; i++) {
        int idx = start + i;
        if (idx < NN) s += g_counts[idx];
    }
    sums[t] = s;
    __syncthreads();
    // Hillis-Steele inclusive scan
    for (int off = 1; off < 1024; off <<= 1) {
        int v = (t >= off) ? sums[t - off] : 0;
        __syncthreads();
        sums[t] += v;
        __syncthreads();
    }
    int run = (t == 0) ? 0 : sums[t - 1];
    for (int i = 0; i < CH; i++) {
        int idx = start + i;
        if (idx < NN) { g_ptr[idx] = run; run += g_counts[idx]; }
    }
    if (t == 1023) g_ptr[NN] = sums[1023];
}

__global__ void __launch_bounds__(256) k_cursor() {
    int i = blockIdx.x * blockDim.x + threadIdx.x;
    if (i < NN) g_cursor[i] = g_ptr[i];
}

__global__ void __launch_bounds__(256) k_fill(const int* __restrict__ src,
                                              const int* __restrict__ dst) {
    int e = blockIdx.x * blockDim.x + threadIdx.x;
    if (e < NE) {
        int s = src[e];
        int d = dst[e];
        int pos = atomicAdd(&g_cursor[d], 1);
        g_csrc[pos] = s;
        g_cw[pos]   = g_dinv[s] * g_dinv[d];
    }
}

// ------------------------------------------------------------------
// GEMM1: h1 = relu(X[100000,512] @ W1[256,512]^T + b1)   (128x128x8 tile)
// ------------------------------------------------------------------
__global__ void __launch_bounds__(256, 2)
k_gemm1(const float* __restrict__ X, const float* __restrict__ W1,
        const float* __restrict__ b1) {
    __shared__ float As[8][128];
    __shared__ float Bs[8][128];
    int tid = threadIdx.x;
    int col0 = blockIdx.x * 128;     // 0 or 128  (F_HID=256)
    int row0 = blockIdx.y * 128;
    int lr = tid >> 1;               // 0..127
    int lk = (tid & 1) * 4;          // 0 or 4
    int tx = tid & 15, ty = tid >> 4;

    float acc[8][8];
#pragma unroll
    for (int i = 0; i < 8; i++)
#pragma unroll
        for (int j = 0; j < 8; j++) acc[i][j] = 0.f;

    const float4 z4 = make_float4(0.f, 0.f, 0.f, 0.f);
    for (int k0 = 0; k0 < F_IN; k0 += 8) {
        int ar = row0 + lr;
        float4 av = (ar < NN) ? *(const float4*)(X + (size_t)ar * F_IN + k0 + lk) : z4;
        float4 bv = *(const float4*)(W1 + (size_t)(col0 + lr) * F_IN + k0 + lk);
        As[lk + 0][lr] = av.x; As[lk + 1][lr] = av.y;
        As[lk + 2][lr] = av.z; As[lk + 3][lr] = av.w;
        Bs[lk + 0][lr] = bv.x; Bs[lk + 1][lr] = bv.y;
        Bs[lk + 2][lr] = bv.z; Bs[lk + 3][lr] = bv.w;
        __syncthreads();
#pragma unroll
        for (int kk = 0; kk < 8; kk++) {
            float4 a0 = *(const float4*)&As[kk][ty * 4];
            float4 a1 = *(const float4*)&As[kk][64 + ty * 4];
            float4 b0 = *(const float4*)&Bs[kk][tx * 4];
            float4 b1f = *(const float4*)&Bs[kk][64 + tx * 4];
            float a[8] = {a0.x, a0.y, a0.z, a0.w, a1.x, a1.y, a1.z, a1.w};
            float b[8] = {b0.x, b0.y, b0.z, b0.w, b1f.x, b1f.y, b1f.z, b1f.w};
#pragma unroll
            for (int i = 0; i < 8; i++)
#pragma unroll
                for (int j = 0; j < 8; j++) acc[i][j] += a[i] * b[j];
        }
        __syncthreads();
    }
#pragma unroll
    for (int i = 0; i < 8; i++) {
        int r = row0 + ((i < 4) ? (ty * 4 + i) : (64 + ty * 4 + (i - 4)));
        if (r >= NN) continue;
#pragma unroll
        for (int j = 0; j < 8; j++) {
            int c = col0 + ((j < 4) ? (tx * 4 + j) : (64 + tx * 4 + (j - 4)));
            float v = acc[i][j] + b1[c];
            g_h1[(size_t)r * F_HID + c] = fmaxf(v, 0.f);
        }
    }
}

// ------------------------------------------------------------------
// GEMM2: h = h1[100000,256] @ W2[16,256]^T + b2
// ------------------------------------------------------------------
__global__ void __launch_bounds__(256) k_gemm2(const float* __restrict__ W2,
                                               const float* __restrict__ b2) {
    __shared__ float w2s[16][260];
    __shared__ float hs[16][260];
    int tid = threadIdx.x;
    for (int idx = tid; idx < 16 * 256; idx += 256)
        w2s[idx >> 8][idx & 255] = W2[idx];
    int row0 = blockIdx.x * 16;
    for (int idx = tid; idx < 16 * 256; idx += 256)
        hs[idx >> 8][idx & 255] =
            g_h1[(size_t)(row0 + (idx >> 8)) * F_HID + (idx & 255)];
    __syncthreads();
    int r = tid >> 4, c = tid & 15;
    const float4* hv = (const float4*)&hs[r][0];
    const float4* wv = (const float4*)&w2s[c][0];
    float acc = b2[c];
#pragma unroll 8
    for (int k = 0; k < 64; k++) {
        float4 h4 = hv[k], w4 = wv[k];
        acc += h4.x * w4.x + h4.y * w4.y + h4.z * w4.z + h4.w * w4.w;
    }
    g_h[(row0 + r) * F_OUT + c] = acc;
}

// ------------------------------------------------------------------
// Propagation step: z_out = (1-a) * A_hat @ z_in + a * h
// 16 threads per node (one per class), CSR gather, no atomics.
// ------------------------------------------------------------------
__global__ void __launch_bounds__(256) k_prop(int in_sel, int out_sel) {
    const float* zin = (in_sel == 0) ? g_h : ((in_sel == 1) ? g_zA : g_zB);
    float* zout = (out_sel == 1) ? g_zA : g_zB;

    int g = blockIdx.x * 16 + (threadIdx.x >> 4);
    int f = threadIdx.x & 15;
    if (g >= NN) return;

    int s = g_ptr[g], e = g_ptr[g + 1];
    float acc = 0.f;
    int j = s;
    for (; j + 1 < e; j += 2) {
        int u0 = g_csrc[j];
        int u1 = g_csrc[j + 1];
        float w0 = g_cw[j];
        float w1 = g_cw[j + 1];
        float v0 = __ldg(&zin[u0 * F_OUT + f]);
        float v1 = __ldg(&zin[u1 * F_OUT + f]);
        acc += w0 * v0 + w1 * v1;
    }
    if (j < e) {
        int u = g_csrc[j];
        acc += g_cw[j] * __ldg(&zin[u * F_OUT + f]);
    }
    float di = g_dinv[g];
    float self = di * di * zin[g * F_OUT + f];
    zout[g * F_OUT + f] = (1.f - ALPHA) * (acc + self) + ALPHA * g_h[g * F_OUT + f];
}

// ------------------------------------------------------------------
// log_softmax over 16 classes (reads final buffer g_zB)
// ------------------------------------------------------------------
__global__ void __launch_bounds__(256) k_logsoftmax(float* __restrict__ out) {
    int g = blockIdx.x * 16 + (threadIdx.x >> 4);
    int f = threadIdx.x & 15;
    if (g >= NN) return;
    float v = g_zB[g * F_OUT + f];
    float m = v;
#pragma unroll
    for (int o = 8; o; o >>= 1)
        m = fmaxf(m, __shfl_xor_sync(0xffffffffu, m, o, 16));
    float ex = expf(v - m);
    float s = ex;
#pragma unroll
    for (int o = 8; o; o >>= 1)
        s += __shfl_xor_sync(0xffffffffu, s, o, 16);
    out[g * F_OUT + f] = v - m - logf(s);
}

// ------------------------------------------------------------------
extern "C" void kernel_launch(void* const* d_in, const int* in_sizes, int n_in,
                              void* d_out, int out_size) {
    const float* x  = (const float*)d_in[0];
    const float* W1 = (const float*)d_in[1];
    const float* b1 = (const float*)d_in[2];
    const float* W2 = (const float*)d_in[3];
    const float* b2 = (const float*)d_in[4];
    const int* ei = (const int*)d_in[5];      // int32! (JAX x64 disabled)
    const int* src = ei;
    const int* dst = ei + NE;
    float* out = (float*)d_out;

    // CSR build (once per launch, amortized over 10 prop steps)
    k_zero_counts<<<(NN + 255) / 256, 256>>>();
    k_count<<<(NE + 255) / 256, 256>>>(dst);
    k_dinv<<<(NN + 255) / 256, 256>>>();
    k_scan<<<1, 1024>>>();
    k_cursor<<<(NN + 255) / 256, 256>>>();
    k_fill<<<(NE + 255) / 256, 256>>>(src, dst);

    // MLP
    dim3 g1(2, (NN + 127) / 128);
    k_gemm1<<<g1, 256>>>(x, W1, b1);
    k_gemm2<<<NN / 16, 256>>>(W2, b2);

    // 10 propagation steps: h -> zA -> zB -> zA ... -> zB (step 9 ends in zB)
    int in_sel = 0;
    for (int s = 0; s < KSTEPS; s++) {
        int out_sel = (s & 1) ? 2 : 1;
        k_prop<<<NN / 16, 256>>>(in_sel, out_sel);
        in_sel = out_sel;
    }

    k_logsoftmax<<<NN / 16, 256>>>(out);
}

// round 4
// speedup vs baseline: 1.7110x; 1.7110x over previous
#include <cuda_runtime.h>
#include <math.h>
#include <stdint.h>

#define NN 100000
#define NE 3200000
#define F_IN 512
#define F_HID 256
#define F_OUT 16
#define KSTEPS 10
#define ALPHA 0.1f

#define NB_SCAN 98              // ceil(100000/1024)
#define MLP_GY 782              // ceil(100000/128)

// ---- static scratch ----
__device__ float g_h    [NN * F_OUT];
__device__ float g_hpart[2][NN * F_OUT];    // per-column-half partial of GEMM2
__device__ float g_zA[NN * F_OUT];
__device__ float g_zB[NN * F_OUT];
__device__ float g_dinv[NN];
__device__ int   g_counts[NN];
__device__ int   g_ptr[NN + 1];
__device__ int   g_cursor[NN];
__device__ int   g_bsums[NB_SCAN];
__device__ int   g_boff [NB_SCAN];
__device__ int   g_csrc[NE];
__device__ float g_cw[NE];

// ------------------------------------------------------------------
// CSR construction (edge_index is int32)
// ------------------------------------------------------------------
__global__ void __launch_bounds__(256) k_zero_counts() {
    int i = blockIdx.x * blockDim.x + threadIdx.x;
    if (i < NN) g_counts[i] = 0;
}

__global__ void __launch_bounds__(256) k_count(const int* __restrict__ dst) {
    int e = blockIdx.x * blockDim.x + threadIdx.x;
    if (e < NE) atomicAdd(&g_counts[dst[e]], 1);
}

__global__ void __launch_bounds__(256) k_dinv() {
    int i = blockIdx.x * blockDim.x + threadIdx.x;
    if (i < NN) g_dinv[i] = rsqrtf((float)(g_counts[i] + 1));
}

// multi-block scan: phase 1 — per-block exclusive scan + block sum
__global__ void __launch_bounds__(1024) k_scan1() {
    __shared__ int s[1024];
    int b = blockIdx.x, t = threadIdx.x;
    int idx = b * 1024 + t;
    int v = (idx < NN) ? g_counts[idx] : 0;
    s[t] = v;
    __syncthreads();
    for (int off = 1; off < 1024; off <<= 1) {
        int u = (t >= off) ? s[t - off] : 0;
        __syncthreads();
        s[t] += u;
        __syncthreads();
    }
    if (idx < NN) g_ptr[idx] = s[t] - v;   // local exclusive
    if (t == 1023) g_bsums[b] = s[1023];
}

// phase 2 — scan the 98 block sums
__global__ void __launch_bounds__(128) k_scan2() {
    __shared__ int s[128];
    int t = threadIdx.x;
    int v = (t < NB_SCAN) ? g_bsums[t] : 0;
    s[t] = v;
    __syncthreads();
    for (int off = 1; off < 128; off <<= 1) {
        int u = (t >= off) ? s[t - off] : 0;
        __syncthreads();
        s[t] += u;
        __syncthreads();
    }
    if (t < NB_SCAN) g_boff[t] = s[t] - v;  // exclusive
    if (t == 127) g_ptr[NN] = s[127];       // total == NE
}

// phase 3 — add block offsets
__global__ void __launch_bounds__(1024) k_scan3() {
    int idx = blockIdx.x * 1024 + threadIdx.x;
    if (idx < NN) {
        int p = g_ptr[idx] + g_boff[blockIdx.x];
        g_ptr[idx] = p;
        g_cursor[idx] = p;
    }
}

__global__ void __launch_bounds__(256) k_fill(const int* __restrict__ src,
                                              const int* __restrict__ dst) {
    int e = blockIdx.x * blockDim.x + threadIdx.x;
    if (e < NE) {
        int s = src[e];
        int d = dst[e];
        int pos = atomicAdd(&g_cursor[d], 1);
        g_csrc[pos] = s;
        g_cw[pos]   = g_dinv[s] * g_dinv[d];
    }
}

// ------------------------------------------------------------------
// Fused MLP: per block computes h1_tile = relu(X[128rows,512] @ W1half^T + b1)
// with TF32 tensor cores, then partial h = h1_tile @ W2half^T into g_hpart.
// grid = (2, 782), block = 256 threads (8 warps, warp grid 4M x 2N, warp tile 32x64)
// ------------------------------------------------------------------
#define XS_STRIDE 36
#define HS_STRIDE 132
#define SMEM_FLOATS (128*XS_STRIDE*2 + 128*HS_STRIDE + 16*HS_STRIDE)
#define SMEM_BYTES  (SMEM_FLOATS * 4)

__device__ __forceinline__ uint32_t f2tf32(float f) {
    uint32_t r;
    asm("cvt.rna.tf32.f32 %0, %1;" : "=r"(r) : "f"(f));
    return r;
}

__device__ __forceinline__ void mma_tf32(float* d, const uint32_t* a, const uint32_t* b) {
    asm volatile(
        "mma.sync.aligned.m16n8k8.row.col.f32.tf32.tf32.f32 "
        "{%0,%1,%2,%3}, {%4,%5,%6,%7}, {%8,%9}, {%0,%1,%2,%3};"
        : "+f"(d[0]), "+f"(d[1]), "+f"(d[2]), "+f"(d[3])
        : "r"(a[0]), "r"(a[1]), "r"(a[2]), "r"(a[3]), "r"(b[0]), "r"(b[1]));
}

__global__ void __launch_bounds__(256)
k_mlp(const float* __restrict__ X, const float* __restrict__ W1,
      const float* __restrict__ b1, const float* __restrict__ W2) {
    extern __shared__ float smem[];
    float* Xs  = smem;                        // [128][36]  (tf32 bits)
    float* Ws  = Xs + 128 * XS_STRIDE;        // [128][36]  (tf32 bits)
    float* Hs  = Ws + 128 * XS_STRIDE;        // [128][132] (fp32 relu tile)
    float* W2s = Hs + 128 * HS_STRIDE;        // [16][132]

    const int tid  = threadIdx.x;
    const int lane = tid & 31;
    const int warp = tid >> 5;
    const int row0 = blockIdx.y * 128;
    const int col0 = blockIdx.x * 128;        // hidden-column half
    const int wm = (warp & 3) * 32;           // warp row offset in tile
    const int wn = (warp >> 2) * 64;          // warp col offset in tile
    const int grp  = lane >> 2;
    const int thr4 = lane & 3;

    // load W2 slice [16][128]
    for (int i = tid; i < 16 * 128; i += 256)
        W2s[(i >> 7) * HS_STRIDE + (i & 127)] = W2[(i >> 7) * F_HID + col0 + (i & 127)];

    float acc[2][8][4];
#pragma unroll
    for (int mt = 0; mt < 2; mt++)
#pragma unroll
        for (int nt = 0; nt < 8; nt++)
#pragma unroll
            for (int q = 0; q < 4; q++) acc[mt][nt][q] = 0.f;

    for (int k0 = 0; k0 < F_IN; k0 += 32) {
        // stage X and W1 tiles (converted to tf32)
#pragma unroll
        for (int it = 0; it < 4; it++) {
            int idx = tid + 256 * it;         // 0..1023
            int m  = idx >> 3;
            int kq = (idx & 7) * 4;
            int gr = row0 + m;
            float4 v = (gr < NN)
                ? *(const float4*)(X + (size_t)gr * F_IN + k0 + kq)
                : make_float4(0.f, 0.f, 0.f, 0.f);
            float4 cv;
            cv.x = __uint_as_float(f2tf32(v.x));
            cv.y = __uint_as_float(f2tf32(v.y));
            cv.z = __uint_as_float(f2tf32(v.z));
            cv.w = __uint_as_float(f2tf32(v.w));
            *(float4*)(Xs + m * XS_STRIDE + kq) = cv;

            float4 w = *(const float4*)(W1 + (size_t)(col0 + m) * F_IN + k0 + kq);
            float4 cw;
            cw.x = __uint_as_float(f2tf32(w.x));
            cw.y = __uint_as_float(f2tf32(w.y));
            cw.z = __uint_as_float(f2tf32(w.z));
            cw.w = __uint_as_float(f2tf32(w.w));
            *(float4*)(Ws + m * XS_STRIDE + kq) = cw;
        }
        __syncthreads();

#pragma unroll
        for (int kk = 0; kk < 32; kk += 8) {
            uint32_t af[2][4], bf[8][2];
#pragma unroll
            for (int mt = 0; mt < 2; mt++) {
                int r = wm + mt * 16 + grp;
                af[mt][0] = __float_as_uint(Xs[r * XS_STRIDE + kk + thr4]);
                af[mt][1] = __float_as_uint(Xs[(r + 8) * XS_STRIDE + kk + thr4]);
                af[mt][2] = __float_as_uint(Xs[r * XS_STRIDE + kk + thr4 + 4]);
                af[mt][3] = __float_as_uint(Xs[(r + 8) * XS_STRIDE + kk + thr4 + 4]);
            }
#pragma unroll
            for (int nt = 0; nt < 8; nt++) {
                int n = wn + nt * 8 + grp;
                bf[nt][0] = __float_as_uint(Ws[n * XS_STRIDE + kk + thr4]);
                bf[nt][1] = __float_as_uint(Ws[n * XS_STRIDE + kk + thr4 + 4]);
            }
#pragma unroll
            for (int mt = 0; mt < 2; mt++)
#pragma unroll
                for (int nt = 0; nt < 8; nt++)
                    mma_tf32(acc[mt][nt], af[mt], bf[nt]);
        }
        __syncthreads();
    }

    // epilogue: relu(acc + b1) -> Hs
#pragma unroll
    for (int mt = 0; mt < 2; mt++) {
        int r = wm + mt * 16 + grp;
#pragma unroll
        for (int nt = 0; nt < 8; nt++) {
            int c = wn + nt * 8 + thr4 * 2;
            float b1a = __ldg(b1 + col0 + c);
            float b1b = __ldg(b1 + col0 + c + 1);
            Hs[r * HS_STRIDE + c]           = fmaxf(acc[mt][nt][0] + b1a, 0.f);
            Hs[r * HS_STRIDE + c + 1]       = fmaxf(acc[mt][nt][1] + b1b, 0.f);
            Hs[(r + 8) * HS_STRIDE + c]     = fmaxf(acc[mt][nt][2] + b1a, 0.f);
            Hs[(r + 8) * HS_STRIDE + c + 1] = fmaxf(acc[mt][nt][3] + b1b, 0.f);
        }
    }
    __syncthreads();

    // GEMM2 partial: [128 rows] x [16 classes] over this block's 128 hidden cols
    {
        int row = tid >> 1;
        int cg  = (tid & 1) * 8;
        int gr  = row0 + row;
        if (gr < NN) {
            float a2[8];
#pragma unroll
            for (int c = 0; c < 8; c++) a2[c] = 0.f;
            for (int k = 0; k < 128; k++) {
                float h = Hs[row * HS_STRIDE + k];
#pragma unroll
                for (int c = 0; c < 8; c++)
                    a2[c] += h * W2s[(cg + c) * HS_STRIDE + k];
            }
#pragma unroll
            for (int c = 0; c < 8; c++)
                g_hpart[blockIdx.x][gr * F_OUT + cg + c] = a2[c];
        }
    }
}

__global__ void __launch_bounds__(256) k_hcombine(const float* __restrict__ b2) {
    int i = blockIdx.x * blockDim.x + threadIdx.x;
    if (i < NN * F_OUT)
        g_h[i] = g_hpart[0][i] + g_hpart[1][i] + __ldg(&b2[i & 15]);
}

// ------------------------------------------------------------------
// Propagation step
// ------------------------------------------------------------------
__global__ void __launch_bounds__(256) k_prop(int in_sel, int out_sel) {
    const float* zin = (in_sel == 0) ? g_h : ((in_sel == 1) ? g_zA : g_zB);
    float* zout = (out_sel == 1) ? g_zA : g_zB;

    int g = blockIdx.x * 16 + (threadIdx.x >> 4);
    int f = threadIdx.x & 15;
    if (g >= NN) return;

    int s = g_ptr[g], e = g_ptr[g + 1];
    float acc = 0.f;
    int j = s;
    for (; j + 1 < e; j += 2) {
        int u0 = g_csrc[j];
        int u1 = g_csrc[j + 1];
        float w0 = g_cw[j];
        float w1 = g_cw[j + 1];
        float v0 = __ldg(&zin[u0 * F_OUT + f]);
        float v1 = __ldg(&zin[u1 * F_OUT + f]);
        acc += w0 * v0 + w1 * v1;
    }
    if (j < e) {
        int u = g_csrc[j];
        acc += g_cw[j] * __ldg(&zin[u * F_OUT + f]);
    }
    float di = g_dinv[g];
    float self = di * di * zin[g * F_OUT + f];
    zout[g * F_OUT + f] = (1.f - ALPHA) * (acc + self) + ALPHA * g_h[g * F_OUT + f];
}

// ------------------------------------------------------------------
__global__ void __launch_bounds__(256) k_logsoftmax(float* __restrict__ out) {
    int g = blockIdx.x * 16 + (threadIdx.x >> 4);
    int f = threadIdx.x & 15;
    if (g >= NN) return;
    float v = g_zB[g * F_OUT + f];
    float m = v;
#pragma unroll
    for (int o = 8; o; o >>= 1)
        m = fmaxf(m, __shfl_xor_sync(0xffffffffu, m, o, 16));
    float ex = expf(v - m);
    float s = ex;
#pragma unroll
    for (int o = 8; o; o >>= 1)
        s += __shfl_xor_sync(0xffffffffu, s, o, 16);
    out[g * F_OUT + f] = v - m - logf(s);
}

// ------------------------------------------------------------------
extern "C" void kernel_launch(void* const* d_in, const int* in_sizes, int n_in,
                              void* d_out, int out_size) {
    const float* x  = (const float*)d_in[0];
    const float* W1 = (const float*)d_in[1];
    const float* b1 = (const float*)d_in[2];
    const float* W2 = (const float*)d_in[3];
    const float* b2 = (const float*)d_in[4];
    const int* ei = (const int*)d_in[5];      // int32 (JAX x64 disabled)
    const int* src = ei;
    const int* dst = ei + NE;
    float* out = (float*)d_out;

    cudaFuncSetAttribute(k_mlp, cudaFuncAttributeMaxDynamicSharedMemorySize, SMEM_BYTES);

    // CSR build
    k_zero_counts<<<(NN + 255) / 256, 256>>>();
    k_count<<<(NE + 255) / 256, 256>>>(dst);
    k_dinv<<<(NN + 255) / 256, 256>>>();
    k_scan1<<<NB_SCAN, 1024>>>();
    k_scan2<<<1, 128>>>();
    k_scan3<<<NB_SCAN, 1024>>>();
    k_fill<<<(NE + 255) / 256, 256>>>(src, dst);

    // fused MLP (tf32 tensor cores) + combine
    dim3 gm(2, MLP_GY);
    k_mlp<<<gm, 256, SMEM_BYTES>>>(x, W1, b1, W2);
    k_hcombine<<<(NN * F_OUT + 255) / 256, 256>>>(b2);

    // 10 propagation steps
    int in_sel = 0;
    for (int s = 0; s < KSTEPS; s++) {
        int out_sel = (s & 1) ? 2 : 1;
        k_prop<<<NN / 16, 256>>>(in_sel, out_sel);
        in_sel = out_sel;
    }

    k_logsoftmax<<<NN / 16, 256>>>(out);
}

// round 5
// speedup vs baseline: 1.8996x; 1.1102x over previous
#include <cuda_runtime.h>
#include <math.h>
#include <stdint.h>

#define NN 100000
#define NE 3200000
#define F_IN 512
#define F_HID 256
#define F_OUT 16
#define KSTEPS 10
#define ALPHA 0.1f

#define NB_SCAN 98              // ceil(100000/1024)
#define MLP_GY 782              // ceil(100000/128)

// ---- static scratch ----
__device__ float g_h    [NN * F_OUT];
__device__ float g_hpart[2][NN * F_OUT];
__device__ float g_zA[NN * F_OUT];
__device__ float g_zB[NN * F_OUT];
__device__ float g_dinv[NN];
__device__ int   g_counts[NN];
__device__ int   g_ptr[NN + 1];
__device__ int   g_cursor[NN];
__device__ int   g_bsums[NB_SCAN];
__device__ int   g_boff [NB_SCAN];
__device__ int2  g_edge[NE];            // packed (src, weight-bits)

// ------------------------------------------------------------------
// CSR construction (edge_index is int32)
// ------------------------------------------------------------------
__global__ void __launch_bounds__(256) k_zero_counts() {
    int i = blockIdx.x * blockDim.x + threadIdx.x;
    if (i < NN) g_counts[i] = 0;
}

__global__ void __launch_bounds__(256) k_count(const int* __restrict__ dst) {
    int e = blockIdx.x * blockDim.x + threadIdx.x;
    if (e < NE) atomicAdd(&g_counts[dst[e]], 1);
}

__global__ void __launch_bounds__(256) k_dinv() {
    int i = blockIdx.x * blockDim.x + threadIdx.x;
    if (i < NN) g_dinv[i] = rsqrtf((float)(g_counts[i] + 1));
}

__global__ void __launch_bounds__(1024) k_scan1() {
    __shared__ int s[1024];
    int b = blockIdx.x, t = threadIdx.x;
    int idx = b * 1024 + t;
    int v = (idx < NN) ? g_counts[idx] : 0;
    s[t] = v;
    __syncthreads();
    for (int off = 1; off < 1024; off <<= 1) {
        int u = (t >= off) ? s[t - off] : 0;
        __syncthreads();
        s[t] += u;
        __syncthreads();
    }
    if (idx < NN) g_ptr[idx] = s[t] - v;
    if (t == 1023) g_bsums[b] = s[1023];
}

__global__ void __launch_bounds__(128) k_scan2() {
    __shared__ int s[128];
    int t = threadIdx.x;
    int v = (t < NB_SCAN) ? g_bsums[t] : 0;
    s[t] = v;
    __syncthreads();
    for (int off = 1; off < 128; off <<= 1) {
        int u = (t >= off) ? s[t - off] : 0;
        __syncthreads();
        s[t] += u;
        __syncthreads();
    }
    if (t < NB_SCAN) g_boff[t] = s[t] - v;
    if (t == 127) g_ptr[NN] = s[127];
}

__global__ void __launch_bounds__(1024) k_scan3() {
    int idx = blockIdx.x * 1024 + threadIdx.x;
    if (idx < NN) {
        int p = g_ptr[idx] + g_boff[blockIdx.x];
        g_ptr[idx] = p;
        g_cursor[idx] = p;
    }
}

__global__ void __launch_bounds__(256) k_fill(const int* __restrict__ src,
                                              const int* __restrict__ dst) {
    int e = blockIdx.x * blockDim.x + threadIdx.x;
    if (e < NE) {
        int s = src[e];
        int d = dst[e];
        int pos = atomicAdd(&g_cursor[d], 1);
        g_edge[pos] = make_int2(s, __float_as_int(g_dinv[s] * g_dinv[d]));
    }
}

// ------------------------------------------------------------------
// Fused MLP (TF32 mma, cp.async 2-stage pipeline)
// grid = (2, 782), block = 256 (8 warps, warp grid 4M x 2N, warp tile 32x64)
// ------------------------------------------------------------------
#define XS_STRIDE 36
#define HS_STRIDE 132
#define STAGE_FLOATS (128 * XS_STRIDE)
#define SMEM_FLOATS (4 * STAGE_FLOATS + 128 * HS_STRIDE + 16 * HS_STRIDE)
#define SMEM_BYTES  (SMEM_FLOATS * 4)

__device__ __forceinline__ uint32_t f2tf32(float f) {
    uint32_t r;
    asm("cvt.rna.tf32.f32 %0, %1;" : "=r"(r) : "f"(f));
    return r;
}

__device__ __forceinline__ void cp_async16(float* smem_dst, const float* gsrc, int src_bytes) {
    uint32_t s = (uint32_t)__cvta_generic_to_shared(smem_dst);
    asm volatile("cp.async.cg.shared.global [%0], [%1], 16, %2;\n"
                 :: "r"(s), "l"(gsrc), "r"(src_bytes));
}
__device__ __forceinline__ void cp_commit() { asm volatile("cp.async.commit_group;\n"); }
__device__ __forceinline__ void cp_wait1() { asm volatile("cp.async.wait_group 1;\n"); }
__device__ __forceinline__ void cp_wait0() { asm volatile("cp.async.wait_group 0;\n"); }

__device__ __forceinline__ void mma_tf32(float* d, const uint32_t* a, const uint32_t* b) {
    asm volatile(
        "mma.sync.aligned.m16n8k8.row.col.f32.tf32.tf32.f32 "
        "{%0,%1,%2,%3}, {%4,%5,%6,%7}, {%8,%9}, {%0,%1,%2,%3};"
        : "+f"(d[0]), "+f"(d[1]), "+f"(d[2]), "+f"(d[3])
        : "r"(a[0]), "r"(a[1]), "r"(a[2]), "r"(a[3]), "r"(b[0]), "r"(b[1]));
}

__global__ void __launch_bounds__(256)
k_mlp(const float* __restrict__ X, const float* __restrict__ W1,
      const float* __restrict__ b1, const float* __restrict__ W2) {
    extern __shared__ float smem[];
    float* Xst = smem;                       // [2][128][36] raw fp32
    float* Wst = smem + 2 * STAGE_FLOATS;    // [2][128][36]
    float* Hs  = smem + 4 * STAGE_FLOATS;    // [128][132]
    float* W2s = Hs + 128 * HS_STRIDE;       // [16][132]

    const int tid  = threadIdx.x;
    const int lane = tid & 31;
    const int warp = tid >> 5;
    const int row0 = blockIdx.y * 128;
    const int col0 = blockIdx.x * 128;
    const int wm = (warp & 3) * 32;
    const int wn = (warp >> 2) * 64;
    const int grp  = lane >> 2;
    const int thr4 = lane & 3;

    for (int i = tid; i < 16 * 128; i += 256)
        W2s[(i >> 7) * HS_STRIDE + (i & 127)] = W2[(i >> 7) * F_HID + col0 + (i & 127)];

    float acc[2][8][4];
#pragma unroll
    for (int mt = 0; mt < 2; mt++)
#pragma unroll
        for (int nt = 0; nt < 8; nt++)
#pragma unroll
            for (int q = 0; q < 4; q++) acc[mt][nt][q] = 0.f;

    // stage lambda: slab s (k = s*32 .. s*32+31) into stage buffer st
    auto stage = [&](int s, int st) {
#pragma unroll
        for (int it = 0; it < 4; it++) {
            int idx = tid + 256 * it;        // 0..1023
            int m  = idx >> 3;
            int kq = (idx & 7) * 4;
            int gr = row0 + m;
            int valid = (gr < NN) ? 16 : 0;
            const float* xs = X + (size_t)((gr < NN) ? gr : 0) * F_IN + s * 32 + kq;
            cp_async16(Xst + st * STAGE_FLOATS + m * XS_STRIDE + kq, xs, valid);
            const float* ws = W1 + (size_t)(col0 + m) * F_IN + s * 32 + kq;
            cp_async16(Wst + st * STAGE_FLOATS + m * XS_STRIDE + kq, ws, 16);
        }
    };

    stage(0, 0);
    cp_commit();

    for (int s = 0; s < 16; s++) {
        int cur = s & 1;
        if (s < 15) {
            stage(s + 1, cur ^ 1);
            cp_commit();
            cp_wait1();
        } else {
            cp_wait0();
        }
        __syncthreads();

        const float* Xs = Xst + cur * STAGE_FLOATS;
        const float* Ws = Wst + cur * STAGE_FLOATS;
#pragma unroll
        for (int kk = 0; kk < 32; kk += 8) {
            uint32_t af[2][4], bf[8][2];
#pragma unroll
            for (int mt = 0; mt < 2; mt++) {
                int r = wm + mt * 16 + grp;
                af[mt][0] = f2tf32(Xs[r * XS_STRIDE + kk + thr4]);
                af[mt][1] = f2tf32(Xs[(r + 8) * XS_STRIDE + kk + thr4]);
                af[mt][2] = f2tf32(Xs[r * XS_STRIDE + kk + thr4 + 4]);
                af[mt][3] = f2tf32(Xs[(r + 8) * XS_STRIDE + kk + thr4 + 4]);
            }
#pragma unroll
            for (int nt = 0; nt < 8; nt++) {
                int n = wn + nt * 8 + grp;
                bf[nt][0] = f2tf32(Ws[n * XS_STRIDE + kk + thr4]);
                bf[nt][1] = f2tf32(Ws[n * XS_STRIDE + kk + thr4 + 4]);
            }
#pragma unroll
            for (int mt = 0; mt < 2; mt++)
#pragma unroll
                for (int nt = 0; nt < 8; nt++)
                    mma_tf32(acc[mt][nt], af[mt], bf[nt]);
        }
        __syncthreads();
    }

    // epilogue: relu(acc + b1) -> Hs
#pragma unroll
    for (int mt = 0; mt < 2; mt++) {
        int r = wm + mt * 16 + grp;
#pragma unroll
        for (int nt = 0; nt < 8; nt++) {
            int c = wn + nt * 8 + thr4 * 2;
            float b1a = __ldg(b1 + col0 + c);
            float b1b = __ldg(b1 + col0 + c + 1);
            Hs[r * HS_STRIDE + c]           = fmaxf(acc[mt][nt][0] + b1a, 0.f);
            Hs[r * HS_STRIDE + c + 1]       = fmaxf(acc[mt][nt][1] + b1b, 0.f);
            Hs[(r + 8) * HS_STRIDE + c]     = fmaxf(acc[mt][nt][2] + b1a, 0.f);
            Hs[(r + 8) * HS_STRIDE + c + 1] = fmaxf(acc[mt][nt][3] + b1b, 0.f);
        }
    }
    __syncthreads();

    // GEMM2 partial
    {
        int row = tid >> 1;
        int cg  = (tid & 1) * 8;
        int gr  = row0 + row;
        if (gr < NN) {
            float a2[8];
#pragma unroll
            for (int c = 0; c < 8; c++) a2[c] = 0.f;
            for (int k = 0; k < 128; k++) {
                float h = Hs[row * HS_STRIDE + k];
#pragma unroll
                for (int c = 0; c < 8; c++)
                    a2[c] += h * W2s[(cg + c) * HS_STRIDE + k];
            }
#pragma unroll
            for (int c = 0; c < 8; c++)
                g_hpart[blockIdx.x][gr * F_OUT + cg + c] = a2[c];
        }
    }
}

__global__ void __launch_bounds__(256) k_hcombine(const float* __restrict__ b2) {
    int i = blockIdx.x * blockDim.x + threadIdx.x;   // over NN*4 float4s
    if (i < NN * 4) {
        const float4* p0 = (const float4*)g_hpart[0];
        const float4* p1 = (const float4*)g_hpart[1];
        const float4* b4 = (const float4*)b2;
        float4 a = p0[i], b = p1[i], c = __ldg(&b4[i & 3]);
        float4 r;
        r.x = a.x + b.x + c.x;
        r.y = a.y + b.y + c.y;
        r.z = a.z + b.z + c.z;
        r.w = a.w + b.w + c.w;
        ((float4*)g_h)[i] = r;
    }
}

// ------------------------------------------------------------------
// Propagation: 4 threads/node, float4 per thread, packed edges
// ------------------------------------------------------------------
__global__ void __launch_bounds__(256) k_prop(int in_sel, int out_sel) {
    const float4* zin4 = (in_sel == 0) ? (const float4*)g_h
                        : ((in_sel == 1) ? (const float4*)g_zA : (const float4*)g_zB);
    float4* zout4 = (out_sel == 1) ? (float4*)g_zA : (float4*)g_zB;

    int node = blockIdx.x * 64 + (threadIdx.x >> 2);
    int tc = threadIdx.x & 3;
    if (node >= NN) return;

    int s = g_ptr[node], e = g_ptr[node + 1];
    float4 acc = make_float4(0.f, 0.f, 0.f, 0.f);
    int j = s;
    for (; j + 1 < e; j += 2) {
        int2 e0 = __ldg(&g_edge[j]);
        int2 e1 = __ldg(&g_edge[j + 1]);
        float w0 = __int_as_float(e0.y);
        float w1 = __int_as_float(e1.y);
        float4 v0 = __ldg(&zin4[e0.x * 4 + tc]);
        float4 v1 = __ldg(&zin4[e1.x * 4 + tc]);
        acc.x += w0 * v0.x + w1 * v1.x;
        acc.y += w0 * v0.y + w1 * v1.y;
        acc.z += w0 * v0.z + w1 * v1.z;
        acc.w += w0 * v0.w + w1 * v1.w;
    }
    if (j < e) {
        int2 e0 = __ldg(&g_edge[j]);
        float w0 = __int_as_float(e0.y);
        float4 v0 = __ldg(&zin4[e0.x * 4 + tc]);
        acc.x += w0 * v0.x;
        acc.y += w0 * v0.y;
        acc.z += w0 * v0.z;
        acc.w += w0 * v0.w;
    }
    float di = g_dinv[node];
    float sw = di * di;
    float4 vs = __ldg(&zin4[node * 4 + tc]);
    float4 hh = __ldg(&((const float4*)g_h)[node * 4 + tc]);
    float4 o;
    o.x = (1.f - ALPHA) * (acc.x + sw * vs.x) + ALPHA * hh.x;
    o.y = (1.f - ALPHA) * (acc.y + sw * vs.y) + ALPHA * hh.y;
    o.z = (1.f - ALPHA) * (acc.z + sw * vs.z) + ALPHA * hh.z;
    o.w = (1.f - ALPHA) * (acc.w + sw * vs.w) + ALPHA * hh.w;
    zout4[node * 4 + tc] = o;
}

// ------------------------------------------------------------------
__global__ void __launch_bounds__(256) k_logsoftmax(float* __restrict__ out) {
    int node = blockIdx.x * 64 + (threadIdx.x >> 2);
    int tc = threadIdx.x & 3;
    if (node >= NN) return;
    float4 v = ((const float4*)g_zB)[node * 4 + tc];
    float m = fmaxf(fmaxf(v.x, v.y), fmaxf(v.z, v.w));
    m = fmaxf(m, __shfl_xor_sync(0xffffffffu, m, 1, 4));
    m = fmaxf(m, __shfl_xor_sync(0xffffffffu, m, 2, 4));
    float s = expf(v.x - m) + expf(v.y - m) + expf(v.z - m) + expf(v.w - m);
    s += __shfl_xor_sync(0xffffffffu, s, 1, 4);
    s += __shfl_xor_sync(0xffffffffu, s, 2, 4);
    float ls = m + logf(s);
    float4 r;
    r.x = v.x - ls; r.y = v.y - ls; r.z = v.z - ls; r.w = v.w - ls;
    ((float4*)out)[node * 4 + tc] = r;
}

// ------------------------------------------------------------------
extern "C" void kernel_launch(void* const* d_in, const int* in_sizes, int n_in,
                              void* d_out, int out_size) {
    const float* x  = (const float*)d_in[0];
    const float* W1 = (const float*)d_in[1];
    const float* b1 = (const float*)d_in[2];
    const float* W2 = (const float*)d_in[3];
    const float* b2 = (const float*)d_in[4];
    const int* ei = (const int*)d_in[5];
    const int* src = ei;
    const int* dst = ei + NE;
    float* out = (float*)d_out;

    cudaFuncSetAttribute(k_mlp, cudaFuncAttributeMaxDynamicSharedMemorySize, SMEM_BYTES);

    // CSR build
    k_zero_counts<<<(NN + 255) / 256, 256>>>();
    k_count<<<(NE + 255) / 256, 256>>>(dst);
    k_dinv<<<(NN + 255) / 256, 256>>>();
    k_scan1<<<NB_SCAN, 1024>>>();
    k_scan2<<<1, 128>>>();
    k_scan3<<<NB_SCAN, 1024>>>();
    k_fill<<<(NE + 255) / 256, 256>>>(src, dst);

    // fused MLP + combine
    dim3 gm(2, MLP_GY);
    k_mlp<<<gm, 256, SMEM_BYTES>>>(x, W1, b1, W2);
    k_hcombine<<<(NN * 4 + 255) / 256, 256>>>(b2);

    // 10 propagation steps
    int in_sel = 0;
    for (int s = 0; s < KSTEPS; s++) {
        int out_sel = (s & 1) ? 2 : 1;
        k_prop<<<(NN + 63) / 64, 256>>>(in_sel, out_sel);
        in_sel = out_sel;
    }

    k_logsoftmax<<<(NN + 63) / 64, 256>>>(out);
}